// round 15
// baseline (speedup 1.0000x reference)
#include <cuda_runtime.h>
#include <cuda_bf16.h>

#define RANK     64
#define WINDOW   11
#define PADR     5
#define TILE     64
#define NTHREADS 256
#define NWARPS   8
#define RPW      8                      // rows per warp
#define XROWS    (TILE + 2 * PADR)      // 74
#define WPITCH   76                     // W pitch: lane*19 mod 8 distinct -> conflict-free LDS.128

typedef unsigned long long ull;

__device__ __forceinline__ ull fma2(ull a, ull b, ull c) {
    ull d; asm("fma.rn.f32x2 %0, %1, %2, %3;" : "=l"(d) : "l"(a), "l"(b), "l"(c)); return d;
}
__device__ __forceinline__ ull mul2(ull a, ull b) {
    ull d; asm("mul.rn.f32x2 %0, %1, %2;" : "=l"(d) : "l"(a), "l"(b)); return d;
}
__device__ __forceinline__ ull pack2(float lo, float hi) {
    ull v; asm("mov.b64 %0, {%1, %2};" : "=l"(v) : "f"(lo), "f"(hi)); return v;
}
__device__ __forceinline__ float2 unpack2(ull v) {
    float lo, hi; asm("mov.b64 {%0, %1}, %2;" : "=f"(lo), "=f"(hi) : "l"(v));
    return make_float2(lo, hi);
}
__device__ __forceinline__ float tanh_fast(float x) {
    float y; asm("tanh.approx.f32 %0, %1;" : "=f"(y) : "f"(x)); return y;
}
__device__ __forceinline__ float ex2_fast(float x) {
    float y; asm("ex2.approx.f32 %0, %1;" : "=f"(y) : "f"(x)); return y;
}

// scores are <x, v>/sqrt(64); fold 1/8 and log2(e) into V so e = ex2(<x, v'>)
#define VSCALE 0.18033688f   // 0.125 * log2(e)

__global__ __launch_bounds__(NTHREADS, 3)
void attn_win_kernel(const float* __restrict__ X,
                     const float* __restrict__ W,
                     const float* __restrict__ bvec,
                     float* __restrict__ out,
                     int L)
{
    __shared__ float xs[XROWS * RANK];     // 18944 B
    __shared__ float wv[RANK * WPITCH];    // 19456 B: W (pitch 76), later reused for V (pitch 64)

    const int tid  = threadIdx.x;
    const int lane = tid & 31;
    const int warp = tid >> 5;
    const int base = blockIdx.x * TILE;

    // ---- stage X tile (zero-padded at edges), coalesced float4 ----
    {
        const float4* X4  = reinterpret_cast<const float4*>(X);
        float4*       xs4 = reinterpret_cast<float4*>(xs);
        #pragma unroll 2
        for (int idx = tid; idx < XROWS * (RANK / 4); idx += NTHREADS) {
            int i  = idx >> 4;
            int ch = idx & 15;
            int g  = base + i - PADR;
            float4 v = make_float4(0.f, 0.f, 0.f, 0.f);
            if (g >= 0 && g < L) v = X4[g * (RANK / 4) + ch];
            xs4[i * (RANK / 4) + ch] = v;
        }
    }
    // ---- stage W into padded-pitch SMEM ----
    {
        const float4* W4 = reinterpret_cast<const float4*>(W);
        for (int idx = tid; idx < RANK * (RANK / 4); idx += NTHREADS) {
            int r  = idx >> 4;
            int ch = idx & 15;
            float4 v = W4[idx];
            *reinterpret_cast<float4*>(&wv[r * WPITCH + ch * 4]) = v;
        }
    }
    __syncthreads();

    const int c0 = lane;
    const int c1 = lane + 32;
    const float bias0 = bvec[c0];
    const float bias1 = bvec[c1];
    const int r0 = warp * RPW;             // local row base for this warp

    // ---- batched GEMV, packed f32x2 with K split into (even,odd) partials ----
    // two row-groups of 4 to cap live accumulator registers at 16
    float v0[RPW], v1[RPW];
    #pragma unroll
    for (int gb = 0; gb < 2; gb++) {
        ull acc0[4], acc1[4];
        #pragma unroll
        for (int r = 0; r < 4; r++) {
            acc0[r] = pack2(bias0, 0.f);
            acc1[r] = pack2(bias1, 0.f);
        }
        #pragma unroll 4
        for (int j = 0; j < RANK / 4; j++) {
            const ulonglong2 a = *reinterpret_cast<const ulonglong2*>(&wv[c0 * WPITCH + j * 4]);
            const ulonglong2 c = *reinterpret_cast<const ulonglong2*>(&wv[c1 * WPITCH + j * 4]);
            #pragma unroll
            for (int r = 0; r < 4; r++) {
                const ulonglong2 xv = *reinterpret_cast<const ulonglong2*>(
                    &xs[(r0 + gb * 4 + r + PADR) * RANK + j * 4]);
                acc0[r] = fma2(xv.x, a.x, acc0[r]);
                acc0[r] = fma2(xv.y, a.y, acc0[r]);
                acc1[r] = fma2(xv.x, c.x, acc1[r]);
                acc1[r] = fma2(xv.y, c.y, acc1[r]);
            }
        }
        #pragma unroll
        for (int r = 0; r < 4; r++) {
            const float2 t0 = unpack2(acc0[r]);
            const float2 t1 = unpack2(acc1[r]);
            v0[gb * 4 + r] = tanh_fast(t0.x + t0.y) * VSCALE;
            v1[gb * 4 + r] = tanh_fast(t1.x + t1.y) * VSCALE;
        }
    }

    __syncthreads();   // all warps done reading W -> wv reusable as V

    // ---- stash scaled V (pitch 64) into the dead W buffer ----
    #pragma unroll
    for (int r = 0; r < RPW; r++) {
        wv[(r0 + r) * RANK + c0] = v0[r];
        wv[(r0 + r) * RANK + c1] = v1[r];
    }
    __syncwarp();

    // ---- group-of-8 layout: 4 groups/warp, group owns one row, lane owns 8 channels ----
    const int grp = lane >> 3;            // 0..3
    const int cA  = (lane & 7) * 4;       // quarter-warp reads 128B contiguous -> conflict-free
    const int cB  = cA + 32;

    #pragma unroll
    for (int b = 0; b < 2; b++) {
        const int lrow = r0 + b * 4 + grp;        // local row 0..63
        const ulonglong2 va = *reinterpret_cast<const ulonglong2*>(&wv[lrow * RANK + cA]);
        const ulonglong2 vb = *reinterpret_cast<const ulonglong2*>(&wv[lrow * RANK + cB]);

        // single-pass softmax-weighted average (|score| < ~5 -> no max subtraction)
        ull oa0 = 0ull, oa1 = 0ull, ob0 = 0ull, ob1 = 0ull;   // (0.f,0.f) bit pattern
        float sum = 0.f;
        #pragma unroll
        for (int w = 0; w < WINDOW; w++) {
            const ulonglong2 xa = *reinterpret_cast<const ulonglong2*>(&xs[(lrow + w) * RANK + cA]);
            const ulonglong2 xb = *reinterpret_cast<const ulonglong2*>(&xs[(lrow + w) * RANK + cB]);
            ull pp = mul2(xa.x, va.x);
            pp = fma2(xa.y, va.y, pp);
            pp = fma2(xb.x, vb.x, pp);
            pp = fma2(xb.y, vb.y, pp);
            const float2 t = unpack2(pp);
            float p = t.x + t.y;
            p += __shfl_xor_sync(0xffffffffu, p, 4);
            p += __shfl_xor_sync(0xffffffffu, p, 2);
            p += __shfl_xor_sync(0xffffffffu, p, 1);
            const float e = ex2_fast(p);          // exp(score) with folded scales
            sum += e;
            const ull e2 = pack2(e, e);
            oa0 = fma2(e2, xa.x, oa0);
            oa1 = fma2(e2, xa.y, oa1);
            ob0 = fma2(e2, xb.x, ob0);
            ob1 = fma2(e2, xb.y, ob1);
        }
        const float inv = __fdividef(1.0f, sum);
        const ull inv2 = pack2(inv, inv);
        ulonglong2 sa, sb;
        sa.x = mul2(oa0, inv2); sa.y = mul2(oa1, inv2);
        sb.x = mul2(ob0, inv2); sb.y = mul2(ob1, inv2);

        const int g = base + lrow;
        if (g < L) {
            *reinterpret_cast<ulonglong2*>(&out[g * RANK + cA]) = sa;   // STG.128
            *reinterpret_cast<ulonglong2*>(&out[g * RANK + cB]) = sb;   // STG.128
        }
    }
}

extern "C" void kernel_launch(void* const* d_in, const int* in_sizes, int n_in,
                              void* d_out, int out_size)
{
    const float* X = (const float*)d_in[0];   // time_factor (L, 64)
    const float* W = (const float*)d_in[1];   // (64, 64)
    const float* b = (const float*)d_in[2];   // (64,)
    float* out = (float*)d_out;               // (L, 64) float32

    const int L    = in_sizes[0] / RANK;
    const int grid = (L + TILE - 1) / TILE;
    attn_win_kernel<<<grid, NTHREADS>>>(X, W, b, out, L);
}